// round 3
// baseline (speedup 1.0000x reference)
#include <cuda_runtime.h>
#include <cuda_bf16.h>
#include <math.h>

// FusionHead: B x {2-token transformer block + heads}, fully fused, fp32 with
// packed f32x2 FFMA2 inner loops (2x fp32 FMA throughput on sm_103a).
//
// Layout per CTA: 16 batch rows -> 32 token-rows (token-major: tr = t*16 + r).
// smem: SA[32][192] residual stream, SB[32][576] scratch (qkv/ffn/etc),
//       SZ[16][192] pooled z.  Total 110,592 B -> 2 CTAs/SM.

#define D 192
#define ROWS 16           // batch rows per CTA
#define TOK 32            // token rows per CTA
#define THREADS 256

typedef unsigned long long u64;

__device__ __forceinline__ void fma2(u64 &d, const u64 a, const u64 b) {
    asm("fma.rn.f32x2 %0, %1, %2, %0;" : "+l"(d) : "l"(a), "l"(b));
}
__device__ __forceinline__ float hsum2(const u64 v) {
    float lo, hi;
    asm("mov.b64 {%0, %1}, %2;" : "=f"(lo), "=f"(hi) : "l"(v));
    return lo + hi;
}

// Register-tiled GEMM stage over smem activations.
// Computes O[r][c] = act(sum_k A[r][k]*W[c][k] + bias[c] (+ R[r][c]))
// Thread grid: tx = lane (32 cols -> 2 cols per thread per 64-col block),
// rowbase..rowbase+NR-1 rows per thread. N % 64 == 0, K % 4 == 0.
template<int NR, bool RELU>
__device__ __forceinline__ void gemm_stage(
    const float* __restrict__ W, const float* __restrict__ bias,
    const float* __restrict__ A, int lda,
    float* __restrict__ O, int ldo,
    const float* __restrict__ R, int ldr,
    int N, int K, int tx, int rowbase)
{
    const int K4 = K >> 2;
    for (int cb = 0; cb < N; cb += 64) {
        const int c0 = cb + tx, c1 = c0 + 32;
        const ulonglong2* __restrict__ w0 =
            reinterpret_cast<const ulonglong2*>(W + (size_t)c0 * K);
        const ulonglong2* __restrict__ w1 =
            reinterpret_cast<const ulonglong2*>(W + (size_t)c1 * K);
        const ulonglong2* __restrict__ a[NR];
        #pragma unroll
        for (int r = 0; r < NR; r++)
            a[r] = reinterpret_cast<const ulonglong2*>(A + (rowbase + r) * lda);

        u64 acc0[NR], acc1[NR];
        #pragma unroll
        for (int r = 0; r < NR; r++) { acc0[r] = 0ULL; acc1[r] = 0ULL; }

        #pragma unroll 4
        for (int k = 0; k < K4; k++) {
            const ulonglong2 wa = w0[k];
            const ulonglong2 wb = w1[k];
            #pragma unroll
            for (int r = 0; r < NR; r++) {
                const ulonglong2 av = a[r][k];
                fma2(acc0[r], av.x, wa.x);
                fma2(acc0[r], av.y, wa.y);
                fma2(acc1[r], av.x, wb.x);
                fma2(acc1[r], av.y, wb.y);
            }
        }
        const float b0 = bias[c0], b1 = bias[c1];
        #pragma unroll
        for (int r = 0; r < NR; r++) {
            float v0 = hsum2(acc0[r]) + b0;
            float v1 = hsum2(acc1[r]) + b1;
            if (R) {
                v0 += R[(rowbase + r) * ldr + c0];
                v1 += R[(rowbase + r) * ldr + c1];
            }
            if (RELU) { v0 = fmaxf(v0, 0.f); v1 = fmaxf(v1, 0.f); }
            O[(rowbase + r) * ldo + c0] = v0;
            O[(rowbase + r) * ldo + c1] = v1;
        }
    }
}

// LayerNorm over 192 dims for `nrows` token-rows (8 warps, 1 row per warp/iter).
__device__ __forceinline__ void layernorm_rows(
    const float* __restrict__ src, int lds,
    float* __restrict__ dst, int ldd,
    const float* __restrict__ g, const float* __restrict__ b,
    int tid)
{
    const int warp = tid >> 5, lane = tid & 31;
    for (int tr = warp; tr < TOK; tr += 8) {
        const float* x = src + tr * lds;
        float v[6], s = 0.f, sq = 0.f;
        #pragma unroll
        for (int j = 0; j < 6; j++) {
            v[j] = x[lane + 32 * j];
            s += v[j];
            sq += v[j] * v[j];
        }
        #pragma unroll
        for (int o = 16; o; o >>= 1) {
            s  += __shfl_xor_sync(0xffffffffu, s,  o);
            sq += __shfl_xor_sync(0xffffffffu, sq, o);
        }
        const float mean = s * (1.f / 192.f);
        const float var  = sq * (1.f / 192.f) - mean * mean;
        const float rs   = rsqrtf(var + 1e-5f);
        #pragma unroll
        for (int j = 0; j < 6; j++) {
            const int c = lane + 32 * j;
            dst[tr * ldd + c] = (v[j] - mean) * rs * g[c] + b[c];
        }
    }
}

__global__ __launch_bounds__(THREADS, 2)
void fusion_head_kernel(
    const float* __restrict__ perc, const float* __restrict__ tech,
    const float* __restrict__ Wp,   const float* __restrict__ bp,
    const float* __restrict__ Wt,   const float* __restrict__ bt,
    const float* __restrict__ in_w, const float* __restrict__ in_b,
    const float* __restrict__ out_w,const float* __restrict__ out_b,
    const float* __restrict__ ffn_w1, const float* __restrict__ ffn_b1,
    const float* __restrict__ ffn_w2, const float* __restrict__ ffn_b2,
    const float* __restrict__ ln1_g, const float* __restrict__ ln1_b,
    const float* __restrict__ ln2_g, const float* __restrict__ ln2_b,
    const float* __restrict__ cls_w1, const float* __restrict__ cls_b1,
    const float* __restrict__ cls_w2, const float* __restrict__ cls_b2,
    const float* __restrict__ fp_w,   const float* __restrict__ fp_b,
    float* __restrict__ out, int B)
{
    extern __shared__ float smem[];
    float* SA = smem;                 // [32][192]
    float* SB = smem + TOK * D;       // [32][576]
    float* SZ = SB + TOK * 576;       // [16][192]

    const int tid = threadIdx.x;
    const int tx = tid & 31, ty = tid >> 5;
    const int rowbase = ty * 4;
    const int block0 = blockIdx.x * ROWS;

    // ---- stage 0: stage inputs into SB[tr][0:192] (token-major) ----
    for (int i = tid; i < TOK * 48; i += THREADS) {
        const int tr = i / 48, k4 = i % 48;
        const int r = (tr < ROWS) ? tr : (tr - ROWS);
        int gr = block0 + r;
        if (gr >= B) gr = B - 1;
        const float* src = (tr < ROWS) ? (perc + (size_t)gr * D)
                                       : (tech + (size_t)gr * D);
        reinterpret_cast<float4*>(SB + tr * 576)[k4] =
            reinterpret_cast<const float4*>(src)[k4];
    }
    __syncthreads();

    // ---- stage 1: input projections -> SA (token 0: Wp, token 1: Wt) ----
    {
        const float* W  = (ty < 4) ? Wp : Wt;
        const float* bb = (ty < 4) ? bp : bt;
        gemm_stage<4, false>(W, bb, SB, 576, SA, D, nullptr, 0, D, D, tx, rowbase);
    }
    __syncthreads();

    // ---- stage 2: packed QKV -> SB[tr][0:576] ----
    gemm_stage<4, false>(in_w, in_b, SA, D, SB, 576, nullptr, 0, 576, D, tx, rowbase);
    __syncthreads();

    // ---- stage 3: 2-token, 3-head attention; ctx overwrites q slots ----
    if (tid < ROWS * 6) {
        const int r = tid / 6, rem = tid % 6;
        const int t = rem & 1, h = rem >> 1;
        const float* q  = SB + (t * ROWS + r) * 576 + h * 64;
        const float* k0 = SB + r * 576 + 192 + h * 64;
        const float* k1 = SB + (ROWS + r) * 576 + 192 + h * 64;
        const float* v0 = SB + r * 576 + 384 + h * 64;
        const float* v1 = SB + (ROWS + r) * 576 + 384 + h * 64;
        float s0 = 0.f, s1 = 0.f;
        #pragma unroll 8
        for (int d = 0; d < 64; d++) {
            const float qd = q[d];
            s0 += qd * k0[d];
            s1 += qd * k1[d];
        }
        s0 *= 0.125f; s1 *= 0.125f;
        const float m = fmaxf(s0, s1);
        const float e0 = expf(s0 - m), e1 = expf(s1 - m);
        const float inv = 1.f / (e0 + e1);
        const float a0 = e0 * inv, a1 = e1 * inv;
        float* ctx = SB + (t * ROWS + r) * 576 + h * 64;  // q slot
        #pragma unroll 8
        for (int d = 0; d < 64; d++) ctx[d] = a0 * v0[d] + a1 * v1[d];
    }
    __syncthreads();

    // ---- stage 4: out-proj + residual(seq in SA) -> SB[tr][384:576] ----
    gemm_stage<4, false>(out_w, out_b, SB, 576, SB + 384, 576, SA, D, D, D, tx, rowbase);
    __syncthreads();

    // ---- stage 5: LN1 -> SA ----
    layernorm_rows(SB + 384, 576, SA, D, ln1_g, ln1_b, tid);
    __syncthreads();

    // ---- stage 6: FFN up + ReLU -> SB[tr][0:384] ----
    gemm_stage<4, true>(ffn_w1, ffn_b1, SA, D, SB, 576, nullptr, 0, 384, D, tx, rowbase);
    __syncthreads();

    // ---- stage 7: FFN down + residual(SA) -> SB[tr][384:576] ----
    gemm_stage<4, false>(ffn_w2, ffn_b2, SB, 576, SB + 384, 576, SA, D, D, 384, tx, rowbase);
    __syncthreads();

    // ---- stage 8: LN2 -> SA ----
    layernorm_rows(SB + 384, 576, SA, D, ln2_g, ln2_b, tid);
    __syncthreads();

    // ---- stage 9: z = mean over 2 tokens -> SZ ----
    for (int i = tid; i < ROWS * 48; i += THREADS) {
        const int r = i / 48, k4 = i % 48;
        const float4 x0 = reinterpret_cast<const float4*>(SA + r * D)[k4];
        const float4 x1 = reinterpret_cast<const float4*>(SA + (ROWS + r) * D)[k4];
        float4 z;
        z.x = 0.5f * (x0.x + x1.x);
        z.y = 0.5f * (x0.y + x1.y);
        z.z = 0.5f * (x0.z + x1.z);
        z.w = 0.5f * (x0.w + x1.w);
        reinterpret_cast<float4*>(SZ + r * D)[k4] = z;
    }
    __syncthreads();

    // ---- stage 10: cls hidden (relu) -> SB[r][0:192]; fp -> SB[r][192:320] ----
    gemm_stage<2, true >(cls_w1, cls_b1, SZ, D, SB,       576, nullptr, 0, D,   D, tx, ty * 2);
    gemm_stage<2, false>(fp_w,   fp_b,   SZ, D, SB + 192, 576, nullptr, 0, 128, D, tx, ty * 2);
    __syncthreads();

    // ---- stage 11: cls logits + sigmoid -> out[j*B + row] ----
    if (tid < ROWS * 3) {
        const int r = tid / 3, j = tid % 3;
        const int gr = block0 + r;
        if (gr < B) {
            const float* hrow = SB + r * 576;
            const float* w = cls_w2 + j * D;
            float s = cls_b2[j];
            #pragma unroll 8
            for (int k = 0; k < D; k++) s += hrow[k] * w[k];
            out[(size_t)j * B + gr] = 1.f / (1.f + expf(-s));
        }
    }

    // ---- stage 12: fingerprint L2-normalize -> out[3B + row*128 + c] ----
    {
        const int warp = ty, lane = tx;
        #pragma unroll
        for (int rr = 0; rr < 2; rr++) {
            const int r = warp * 2 + rr;
            const int gr = block0 + r;
            const float* f = SB + r * 576 + 192;
            float v[4], sq = 0.f;
            #pragma unroll
            for (int j = 0; j < 4; j++) {
                v[j] = f[lane + 32 * j];
                sq += v[j] * v[j];
            }
            #pragma unroll
            for (int o = 16; o; o >>= 1)
                sq += __shfl_xor_sync(0xffffffffu, sq, o);
            const float inv = 1.f / fmaxf(sqrtf(sq), 1e-12f);
            if (gr < B) {
                float* o = out + (size_t)3 * B + (size_t)gr * 128;
                #pragma unroll
                for (int j = 0; j < 4; j++) o[lane + 32 * j] = v[j] * inv;
            }
        }
    }
}

extern "C" void kernel_launch(void* const* d_in, const int* in_sizes, int n_in,
                              void* d_out, int out_size)
{
    const float* perc   = (const float*)d_in[0];
    const float* tech   = (const float*)d_in[1];
    const float* Wp     = (const float*)d_in[2];
    const float* bp     = (const float*)d_in[3];
    const float* Wt     = (const float*)d_in[4];
    const float* bt     = (const float*)d_in[5];
    const float* in_w   = (const float*)d_in[6];
    const float* in_b   = (const float*)d_in[7];
    const float* out_w  = (const float*)d_in[8];
    const float* out_b  = (const float*)d_in[9];
    const float* ffn_w1 = (const float*)d_in[10];
    const float* ffn_b1 = (const float*)d_in[11];
    const float* ffn_w2 = (const float*)d_in[12];
    const float* ffn_b2 = (const float*)d_in[13];
    const float* ln1_g  = (const float*)d_in[14];
    const float* ln1_b  = (const float*)d_in[15];
    const float* ln2_g  = (const float*)d_in[16];
    const float* ln2_b  = (const float*)d_in[17];
    const float* cls_w1 = (const float*)d_in[18];
    const float* cls_b1 = (const float*)d_in[19];
    const float* cls_w2 = (const float*)d_in[20];
    const float* cls_b2 = (const float*)d_in[21];
    const float* fp_w   = (const float*)d_in[22];
    const float* fp_b   = (const float*)d_in[23];

    const int B = in_sizes[0] / D;
    const size_t SMEM = (size_t)(TOK * D + TOK * 576 + ROWS * D) * sizeof(float);

    cudaFuncSetAttribute(fusion_head_kernel,
                         cudaFuncAttributeMaxDynamicSharedMemorySize, (int)SMEM);

    const int grid = (B + ROWS - 1) / ROWS;
    fusion_head_kernel<<<grid, THREADS, SMEM>>>(
        perc, tech, Wp, bp, Wt, bt, in_w, in_b, out_w, out_b,
        ffn_w1, ffn_b1, ffn_w2, ffn_b2, ln1_g, ln1_b, ln2_g, ln2_b,
        cls_w1, cls_b1, cls_w2, cls_b2, fp_w, fp_b,
        (float*)d_out, B);
}

// round 5
// speedup vs baseline: 2.1924x; 2.1924x over previous
#include <cuda_runtime.h>
#include <cuda_bf16.h>
#include <math.h>

// FusionHead fully fused, fp32 + packed f32x2 FMA.
// Design: lane = token-row, warp = 12-column slice, column blocks of 96.
//   - Activations: per-lane LDS.128 from padded smem rows (conflict-free).
//   - Weights: uniform (warp-broadcast) LDG.128 from global, L1/L2 resident.
// R4 fixes R3's coverage bug (warps covered 12 of 24 assigned columns).

#define D 192
#define ROWS 16           // batch rows per CTA
#define TOK 32            // token rows per CTA
#define THREADS 256
#define LDA 196           // SA row pitch (words): 196 % 32 == 4 -> conflict-free LDS.128
#define LDB 580           // SB row pitch (words): 580 % 32 == 4

typedef unsigned long long u64;

__device__ __forceinline__ void fma2(u64 &d, const u64 a, const u64 b) {
    asm("fma.rn.f32x2 %0, %1, %2, %0;" : "+l"(d) : "l"(a), "l"(b));
}
__device__ __forceinline__ float hsum2(const u64 v) {
    float lo, hi;
    asm("mov.b64 {%0, %1}, %2;" : "=f"(lo), "=f"(hi) : "l"(v));
    return lo + hi;
}
__device__ __forceinline__ u64 pack2(const float lo, const float hi) {
    u64 r;
    asm("mov.b64 %0, {%1, %2};" : "=l"(r) : "f"(lo), "f"(hi));
    return r;
}

// One thread computes C output columns for ONE activation row.
//   Wc    -> W[c0][0]   (row-major, stride K) — warp-uniform (or 2-way) address
//   Arow  -> this thread's activation row in smem (16B aligned, contiguous K)
//   Orow  -> &O[row][c0]
//   Rrow  -> residual &R[row][c0] or nullptr
template<int C, int K, bool RELU>
__device__ __forceinline__ void gemm_b(
    const float* __restrict__ Wc, const float* __restrict__ biasc,
    const float* __restrict__ Arow,
    float* __restrict__ Orow, const float* __restrict__ Rrow)
{
    u64 acc[C];
    #pragma unroll
    for (int c = 0; c < C; c++) acc[c] = 0ULL;

    const float4* __restrict__ a4 = reinterpret_cast<const float4*>(Arow);
    #pragma unroll 2
    for (int k = 0; k < (K >> 2); k++) {
        const float4 av = a4[k];
        const u64 alo = pack2(av.x, av.y);
        const u64 ahi = pack2(av.z, av.w);
        #pragma unroll
        for (int c = 0; c < C; c++) {
            const float4 wv =
                *reinterpret_cast<const float4*>(Wc + c * K + (k << 2));
            fma2(acc[c], alo, pack2(wv.x, wv.y));
            fma2(acc[c], ahi, pack2(wv.z, wv.w));
        }
    }
    #pragma unroll
    for (int c = 0; c < C; c++) {
        float v = hsum2(acc[c]) + biasc[c];
        if (Rrow) v += Rrow[c];
        if (RELU) v = fmaxf(v, 0.f);
        Orow[c] = v;
    }
}

// LayerNorm over 192 dims (warp per token-row, lanes over cols).
__device__ __forceinline__ void layernorm_rows(
    const float* __restrict__ src, int lds,
    float* __restrict__ dst, int ldd,
    const float* __restrict__ g, const float* __restrict__ b,
    int tid)
{
    const int warp = tid >> 5, lane = tid & 31;
    for (int tr = warp; tr < TOK; tr += 8) {
        const float* x = src + tr * lds;
        float v[6], s = 0.f, sq = 0.f;
        #pragma unroll
        for (int j = 0; j < 6; j++) {
            v[j] = x[lane + 32 * j];
            s += v[j];
            sq += v[j] * v[j];
        }
        #pragma unroll
        for (int o = 16; o; o >>= 1) {
            s  += __shfl_xor_sync(0xffffffffu, s,  o);
            sq += __shfl_xor_sync(0xffffffffu, sq, o);
        }
        const float mean = s * (1.f / 192.f);
        const float var  = sq * (1.f / 192.f) - mean * mean;
        const float rs   = rsqrtf(var + 1e-5f);
        #pragma unroll
        for (int j = 0; j < 6; j++) {
            const int c = lane + 32 * j;
            dst[tr * ldd + c] = (v[j] - mean) * rs * g[c] + b[c];
        }
    }
}

__global__ __launch_bounds__(THREADS, 2)
void fusion_head_kernel(
    const float* __restrict__ perc, const float* __restrict__ tech,
    const float* __restrict__ Wp,   const float* __restrict__ bp,
    const float* __restrict__ Wt,   const float* __restrict__ bt,
    const float* __restrict__ in_w, const float* __restrict__ in_b,
    const float* __restrict__ out_w,const float* __restrict__ out_b,
    const float* __restrict__ ffn_w1, const float* __restrict__ ffn_b1,
    const float* __restrict__ ffn_w2, const float* __restrict__ ffn_b2,
    const float* __restrict__ ln1_g, const float* __restrict__ ln1_b,
    const float* __restrict__ ln2_g, const float* __restrict__ ln2_b,
    const float* __restrict__ cls_w1, const float* __restrict__ cls_b1,
    const float* __restrict__ cls_w2, const float* __restrict__ cls_b2,
    const float* __restrict__ fp_w,   const float* __restrict__ fp_b,
    float* __restrict__ out, int B)
{
    extern __shared__ float smem[];
    float* SA = smem;                 // [32][LDA] residual / LN stream
    float* SB = smem + TOK * LDA;     // [32][LDB] scratch

    const int tid  = threadIdx.x;
    const int lane = tid & 31;        // == token-row for main GEMMs
    const int warp = tid >> 5;        // 0..7, owns a 12-column slice per block
    const int block0 = blockIdx.x * ROWS;

    // ---- stage 0: stage inputs into SB[tr][0:192] (tr<16: perc, else tech) --
    for (int i = tid; i < TOK * 48; i += THREADS) {
        const int tr = i / 48, k4 = i % 48;
        const int r = (tr < ROWS) ? tr : (tr - ROWS);
        int gr = block0 + r;
        if (gr >= B) gr = B - 1;
        const float* src = (tr < ROWS) ? (perc + (size_t)gr * D)
                                       : (tech + (size_t)gr * D);
        reinterpret_cast<float4*>(SB + tr * LDB)[k4] =
            reinterpret_cast<const float4*>(src)[k4];
    }
    __syncthreads();

    // ---- stage 1: input projections -> SA (token0: Wp, token1: Wt) --------
    {
        const float* W  = (lane < ROWS) ? Wp : Wt;   // 2 uniform addrs / warp
        const float* bb = (lane < ROWS) ? bp : bt;
        #pragma unroll
        for (int cb = 0; cb < 192; cb += 96) {
            const int c0 = cb + warp * 12;
            gemm_b<12, 192, false>(W + c0 * 192, bb + c0,
                                   SB + lane * LDB,
                                   SA + lane * LDA + c0, nullptr);
        }
    }
    __syncthreads();

    // ---- stage 2: packed QKV -> SB[tr][0:576] ------------------------------
    #pragma unroll
    for (int cb = 0; cb < 576; cb += 96) {
        const int c0 = cb + warp * 12;
        gemm_b<12, 192, false>(in_w + c0 * 192, in_b + c0,
                               SA + lane * LDA,
                               SB + lane * LDB + c0, nullptr);
    }
    __syncthreads();

    // ---- stage 3: 2-token, 3-head attention; ctx overwrites q slots --------
    if (tid < ROWS * 6) {
        const int r = tid / 6, rem = tid % 6;
        const int t = rem & 1, h = rem >> 1;
        const float* q  = SB + (t * ROWS + r) * LDB + h * 64;
        const float* k0 = SB + r * LDB + 192 + h * 64;
        const float* k1 = SB + (ROWS + r) * LDB + 192 + h * 64;
        const float* v0 = SB + r * LDB + 384 + h * 64;
        const float* v1 = SB + (ROWS + r) * LDB + 384 + h * 64;
        float s0 = 0.f, s1 = 0.f;
        #pragma unroll 8
        for (int d = 0; d < 64; d++) {
            const float qd = q[d];
            s0 += qd * k0[d];
            s1 += qd * k1[d];
        }
        s0 *= 0.125f; s1 *= 0.125f;
        const float m = fmaxf(s0, s1);
        const float e0 = expf(s0 - m), e1 = expf(s1 - m);
        const float inv = 1.f / (e0 + e1);
        const float a0 = e0 * inv, a1 = e1 * inv;
        float* ctx = SB + (t * ROWS + r) * LDB + h * 64;  // q slot
        #pragma unroll 8
        for (int d = 0; d < 64; d++) ctx[d] = a0 * v0[d] + a1 * v1[d];
    }
    __syncthreads();

    // ---- stage 4: out-proj + residual(SA) -> SB[tr][384:576] --------------
    #pragma unroll
    for (int cb = 0; cb < 192; cb += 96) {
        const int c0 = cb + warp * 12;
        gemm_b<12, 192, false>(out_w + c0 * 192, out_b + c0,
                               SB + lane * LDB,
                               SB + lane * LDB + 384 + c0,
                               SA + lane * LDA + c0);
    }
    __syncthreads();

    // ---- stage 5: LN1 -> SA ------------------------------------------------
    layernorm_rows(SB + 384, LDB, SA, LDA, ln1_g, ln1_b, tid);
    __syncthreads();

    // ---- stage 6: FFN up + ReLU -> SB[tr][0:384] ---------------------------
    #pragma unroll
    for (int cb = 0; cb < 384; cb += 96) {
        const int c0 = cb + warp * 12;
        gemm_b<12, 192, true>(ffn_w1 + c0 * 192, ffn_b1 + c0,
                              SA + lane * LDA,
                              SB + lane * LDB + c0, nullptr);
    }
    __syncthreads();

    // ---- stage 7: FFN down (K=384) + residual(SA) -> SB[tr][384:576] -------
    #pragma unroll
    for (int cb = 0; cb < 192; cb += 96) {
        const int c0 = cb + warp * 12;
        gemm_b<12, 384, false>(ffn_w2 + c0 * 384, ffn_b2 + c0,
                               SB + lane * LDB,
                               SB + lane * LDB + 384 + c0,
                               SA + lane * LDA + c0);
    }
    __syncthreads();

    // ---- stage 8: LN2 -> SA ------------------------------------------------
    layernorm_rows(SB + 384, LDB, SA, LDA, ln2_g, ln2_b, tid);
    __syncthreads();

    // ---- stage 9: z = mean over 2 tokens -> SB[r][384:576] -----------------
    for (int i = tid; i < ROWS * 48; i += THREADS) {
        const int r = i / 48, k4 = i % 48;
        const float4 x0 = reinterpret_cast<const float4*>(SA + r * LDA)[k4];
        const float4 x1 = reinterpret_cast<const float4*>(SA + (ROWS + r) * LDA)[k4];
        float4 z;
        z.x = 0.5f * (x0.x + x1.x);
        z.y = 0.5f * (x0.y + x1.y);
        z.z = 0.5f * (x0.z + x1.z);
        z.w = 0.5f * (x0.w + x1.w);
        reinterpret_cast<float4*>(SB + r * LDB + 384)[k4] = z;
    }
    __syncthreads();

    // ---- stage 10: heads. 16 rows -> row = lane&15, col-half = lane>>4 -----
    {
        const int r  = lane & 15;
        const int hf = lane >> 4;
        const float* zrow = SB + r * LDB + 384;

        // cls hidden (relu): 192 cols, 24/warp, 12 per half -> SB[r][0:192]
        {
            const int c0 = warp * 24 + hf * 12;
            gemm_b<12, 192, true>(cls_w1 + c0 * 192, cls_b1 + c0,
                                  zrow, SB + r * LDB + c0, nullptr);
        }
        // fingerprint: 128 cols, 16/warp, 8 per half -> SB[r][192:320]
        {
            const int c0 = warp * 16 + hf * 8;
            gemm_b<8, 192, false>(fp_w + c0 * 192, fp_b + c0,
                                  zrow, SB + r * LDB + 192 + c0, nullptr);
        }
    }
    __syncthreads();

    // ---- stage 11: cls logits + sigmoid -> out[j*B + row] ------------------
    if (tid < ROWS * 3) {
        const int r = tid / 3, j = tid % 3;
        const int gr = block0 + r;
        if (gr < B) {
            const float* hrow = SB + r * LDB;
            const float* w = cls_w2 + j * D;
            float s = cls_b2[j];
            #pragma unroll 8
            for (int k = 0; k < D; k++) s += hrow[k] * w[k];
            out[(size_t)j * B + gr] = 1.f / (1.f + expf(-s));
        }
    }

    // ---- stage 12: fingerprint L2-normalize -> out[3B + row*128 + c] -------
    {
        #pragma unroll
        for (int rr = 0; rr < 2; rr++) {
            const int r = warp * 2 + rr;
            const int gr = block0 + r;
            const float* f = SB + r * LDB + 192;
            float v[4], sq = 0.f;
            #pragma unroll
            for (int j = 0; j < 4; j++) {
                v[j] = f[lane + 32 * j];
                sq += v[j] * v[j];
            }
            #pragma unroll
            for (int o = 16; o; o >>= 1)
                sq += __shfl_xor_sync(0xffffffffu, sq, o);
            const float inv = 1.f / fmaxf(sqrtf(sq), 1e-12f);
            if (gr < B) {
                float* o = out + (size_t)3 * B + (size_t)gr * 128;
                #pragma unroll
                for (int j = 0; j < 4; j++) o[lane + 32 * j] = v[j] * inv;
            }
        }
    }
}

extern "C" void kernel_launch(void* const* d_in, const int* in_sizes, int n_in,
                              void* d_out, int out_size)
{
    const float* perc   = (const float*)d_in[0];
    const float* tech   = (const float*)d_in[1];
    const float* Wp     = (const float*)d_in[2];
    const float* bp     = (const float*)d_in[3];
    const float* Wt     = (const float*)d_in[4];
    const float* bt     = (const float*)d_in[5];
    const float* in_w   = (const float*)d_in[6];
    const float* in_b   = (const float*)d_in[7];
    const float* out_w  = (const float*)d_in[8];
    const float* out_b  = (const float*)d_in[9];
    const float* ffn_w1 = (const float*)d_in[10];
    const float* ffn_b1 = (const float*)d_in[11];
    const float* ffn_w2 = (const float*)d_in[12];
    const float* ffn_b2 = (const float*)d_in[13];
    const float* ln1_g  = (const float*)d_in[14];
    const float* ln1_b  = (const float*)d_in[15];
    const float* ln2_g  = (const float*)d_in[16];
    const float* ln2_b  = (const float*)d_in[17];
    const float* cls_w1 = (const float*)d_in[18];
    const float* cls_b1 = (const float*)d_in[19];
    const float* cls_w2 = (const float*)d_in[20];
    const float* cls_b2 = (const float*)d_in[21];
    const float* fp_w   = (const float*)d_in[22];
    const float* fp_b   = (const float*)d_in[23];

    const int B = in_sizes[0] / D;
    const size_t SMEM = (size_t)(TOK * LDA + TOK * LDB) * sizeof(float);

    cudaFuncSetAttribute(fusion_head_kernel,
                         cudaFuncAttributeMaxDynamicSharedMemorySize, (int)SMEM);

    const int grid = (B + ROWS - 1) / ROWS;
    fusion_head_kernel<<<grid, THREADS, SMEM>>>(
        perc, tech, Wp, bp, Wt, bt, in_w, in_b, out_w, out_b,
        ffn_w1, ffn_b1, ffn_w2, ffn_b2, ln1_g, ln1_b, ln2_g, ln2_b,
        cls_w1, cls_b1, cls_w2, cls_b2, fp_w, fp_b,
        (float*)d_out, B);
}

// round 7
// speedup vs baseline: 4.5181x; 2.0608x over previous
#include <cuda_runtime.h>
#include <cuda_bf16.h>
#include <math.h>

// FusionHead fully fused, fp32 + packed f32x2 FMA.
// R5: register outer-product tiling — each thread computes 4 rows x 6 cols,
// raising fma2-per-load from 1.85 (R4) to 4.8 to escape the L1 wavefront bound.
//   lane = (cs = lane>>3 : column subset, rg = lane&7 : row group)
//   rows {rg, rg+8, rg+16, rg+24} (stride 8 -> conflict-free smem quads, LDA/4 odd)
//   cols warp*24 + cs*6 + j  (8 warps x 24 = 192-col pass)

#define D 192
#define ROWS 16           // batch rows per CTA
#define TOK 32            // token rows per CTA
#define THREADS 256
#define LDA 196           // SA pitch (words): /4 = 49 (odd) -> conflict-free
#define LDB 580           // SB pitch (words): /4 = 145 (odd)

typedef unsigned long long u64;

__device__ __forceinline__ void fma2(u64 &d, const u64 a, const u64 b) {
    asm("fma.rn.f32x2 %0, %1, %2, %0;" : "+l"(d) : "l"(a), "l"(b));
}
__device__ __forceinline__ float hsum2(const u64 v) {
    float lo, hi;
    asm("mov.b64 {%0, %1}, %2;" : "=f"(lo), "=f"(hi) : "l"(v));
    return lo + hi;
}
__device__ __forceinline__ u64 pack2(const float lo, const float hi) {
    u64 r;
    asm("mov.b64 %0, {%1, %2};" : "=l"(r) : "f"(lo), "f"(hi));
    return r;
}

// 4-row x 6-col register tile GEMM.
//   W01/b01: weights+bias for rows rg, rg+8   (token 0 in stage 1)
//   W23/b23: weights+bias for rows rg+16,+24  (token 1 in stage 1)
//   (W01==W23 in all other stages; DUAL=false skips the second load)
// A rows at Asm + r*ldaw (16B-aligned), K contiguous. c0 = this thread's col.
template<int K4, bool RELU, bool DUAL, bool RES>
__device__ __forceinline__ void gemm_tile(
    const float* __restrict__ W01, const float* __restrict__ W23,
    const float* __restrict__ b01, const float* __restrict__ b23,
    const float* __restrict__ Asm, int ldaw,
    float* __restrict__ Osm, int ldow,
    const float* __restrict__ Rsm, int ldrw,
    int c0, int rg)
{
    u64 acc[4][6];
    #pragma unroll
    for (int i = 0; i < 4; i++)
        #pragma unroll
        for (int j = 0; j < 6; j++) acc[i][j] = 0ULL;

    const float4* __restrict__ a0 = reinterpret_cast<const float4*>(Asm + rg * ldaw);
    const float4* __restrict__ a1 = reinterpret_cast<const float4*>(Asm + (rg + 8) * ldaw);
    const float4* __restrict__ a2 = reinterpret_cast<const float4*>(Asm + (rg + 16) * ldaw);
    const float4* __restrict__ a3 = reinterpret_cast<const float4*>(Asm + (rg + 24) * ldaw);
    const float4* __restrict__ w01 = reinterpret_cast<const float4*>(W01) + (size_t)c0 * K4;
    const float4* __restrict__ w23 = reinterpret_cast<const float4*>(W23) + (size_t)c0 * K4;

    #pragma unroll 2
    for (int k = 0; k < K4; k++) {
        const float4 av0 = a0[k], av1 = a1[k], av2 = a2[k], av3 = a3[k];
        const u64 lo0 = pack2(av0.x, av0.y), hi0 = pack2(av0.z, av0.w);
        const u64 lo1 = pack2(av1.x, av1.y), hi1 = pack2(av1.z, av1.w);
        const u64 lo2 = pack2(av2.x, av2.y), hi2 = pack2(av2.z, av2.w);
        const u64 lo3 = pack2(av3.x, av3.y), hi3 = pack2(av3.z, av3.w);
        #pragma unroll
        for (int j = 0; j < 6; j++) {
            const float4 w = w01[j * K4 + k];
            const u64 wlo = pack2(w.x, w.y), whi = pack2(w.z, w.w);
            fma2(acc[0][j], lo0, wlo); fma2(acc[0][j], hi0, whi);
            fma2(acc[1][j], lo1, wlo); fma2(acc[1][j], hi1, whi);
            u64 wlo2, whi2;
            if (DUAL) {
                const float4 w2 = w23[j * K4 + k];
                wlo2 = pack2(w2.x, w2.y); whi2 = pack2(w2.z, w2.w);
            } else { wlo2 = wlo; whi2 = whi; }
            fma2(acc[2][j], lo2, wlo2); fma2(acc[2][j], hi2, whi2);
            fma2(acc[3][j], lo3, wlo2); fma2(acc[3][j], hi3, whi2);
        }
    }

    #pragma unroll
    for (int j = 0; j < 6; j++) {
        const int c = c0 + j;
        float v0 = hsum2(acc[0][j]) + b01[c];
        float v1 = hsum2(acc[1][j]) + b01[c];
        float v2 = hsum2(acc[2][j]) + b23[c];
        float v3 = hsum2(acc[3][j]) + b23[c];
        if (RES) {
            v0 += Rsm[rg * ldrw + c];
            v1 += Rsm[(rg + 8) * ldrw + c];
            v2 += Rsm[(rg + 16) * ldrw + c];
            v3 += Rsm[(rg + 24) * ldrw + c];
        }
        if (RELU) {
            v0 = fmaxf(v0, 0.f); v1 = fmaxf(v1, 0.f);
            v2 = fmaxf(v2, 0.f); v3 = fmaxf(v3, 0.f);
        }
        Osm[rg * ldow + c]        = v0;
        Osm[(rg + 8) * ldow + c]  = v1;
        Osm[(rg + 16) * ldow + c] = v2;
        Osm[(rg + 24) * ldow + c] = v3;
    }
}

// Head-stage GEMM (small): one thread, C cols for one activation row.
template<int C, int K, bool RELU>
__device__ __forceinline__ void gemm_b(
    const float* __restrict__ Wc, const float* __restrict__ biasc,
    const float* __restrict__ Arow,
    float* __restrict__ Orow)
{
    u64 acc[C];
    #pragma unroll
    for (int c = 0; c < C; c++) acc[c] = 0ULL;
    const float4* __restrict__ a4 = reinterpret_cast<const float4*>(Arow);
    #pragma unroll 2
    for (int k = 0; k < (K >> 2); k++) {
        const float4 av = a4[k];
        const u64 alo = pack2(av.x, av.y);
        const u64 ahi = pack2(av.z, av.w);
        #pragma unroll
        for (int c = 0; c < C; c++) {
            const float4 wv = *reinterpret_cast<const float4*>(Wc + c * K + (k << 2));
            fma2(acc[c], alo, pack2(wv.x, wv.y));
            fma2(acc[c], ahi, pack2(wv.z, wv.w));
        }
    }
    #pragma unroll
    for (int c = 0; c < C; c++) {
        float v = hsum2(acc[c]) + biasc[c];
        if (RELU) v = fmaxf(v, 0.f);
        Orow[c] = v;
    }
}

__device__ __forceinline__ void layernorm_rows(
    const float* __restrict__ src, int lds,
    float* __restrict__ dst, int ldd,
    const float* __restrict__ g, const float* __restrict__ b,
    int tid)
{
    const int warp = tid >> 5, lane = tid & 31;
    for (int tr = warp; tr < TOK; tr += 8) {
        const float* x = src + tr * lds;
        float v[6], s = 0.f, sq = 0.f;
        #pragma unroll
        for (int j = 0; j < 6; j++) {
            v[j] = x[lane + 32 * j];
            s += v[j];
            sq += v[j] * v[j];
        }
        #pragma unroll
        for (int o = 16; o; o >>= 1) {
            s  += __shfl_xor_sync(0xffffffffu, s,  o);
            sq += __shfl_xor_sync(0xffffffffu, sq, o);
        }
        const float mean = s * (1.f / 192.f);
        const float var  = sq * (1.f / 192.f) - mean * mean;
        const float rs   = rsqrtf(var + 1e-5f);
        #pragma unroll
        for (int j = 0; j < 6; j++) {
            const int c = lane + 32 * j;
            dst[tr * ldd + c] = (v[j] - mean) * rs * g[c] + b[c];
        }
    }
}

__global__ __launch_bounds__(THREADS, 2)
void fusion_head_kernel(
    const float* __restrict__ perc, const float* __restrict__ tech,
    const float* __restrict__ Wp,   const float* __restrict__ bp,
    const float* __restrict__ Wt,   const float* __restrict__ bt,
    const float* __restrict__ in_w, const float* __restrict__ in_b,
    const float* __restrict__ out_w,const float* __restrict__ out_b,
    const float* __restrict__ ffn_w1, const float* __restrict__ ffn_b1,
    const float* __restrict__ ffn_w2, const float* __restrict__ ffn_b2,
    const float* __restrict__ ln1_g, const float* __restrict__ ln1_b,
    const float* __restrict__ ln2_g, const float* __restrict__ ln2_b,
    const float* __restrict__ cls_w1, const float* __restrict__ cls_b1,
    const float* __restrict__ cls_w2, const float* __restrict__ cls_b2,
    const float* __restrict__ fp_w,   const float* __restrict__ fp_b,
    float* __restrict__ out, int B)
{
    extern __shared__ float smem[];
    float* SA = smem;                 // [32][LDA] residual / LN stream
    float* SB = smem + TOK * LDA;     // [32][LDB] scratch

    const int tid  = threadIdx.x;
    const int lane = tid & 31;
    const int warp = tid >> 5;
    const int cs   = lane >> 3;       // column subset 0..3
    const int rg   = lane & 7;        // row group 0..7
    const int cbase = warp * 24 + cs * 6;
    const int block0 = blockIdx.x * ROWS;

    // ---- stage 0: stage inputs into SB[tr][0:192] (tr<16: perc, else tech) --
    for (int i = tid; i < TOK * 48; i += THREADS) {
        const int tr = i / 48, k4 = i % 48;
        const int r = (tr < ROWS) ? tr : (tr - ROWS);
        int gr = block0 + r;
        if (gr >= B) gr = B - 1;
        const float* src = (tr < ROWS) ? (perc + (size_t)gr * D)
                                       : (tech + (size_t)gr * D);
        reinterpret_cast<float4*>(SB + tr * LDB)[k4] =
            reinterpret_cast<const float4*>(src)[k4];
    }
    __syncthreads();

    // ---- stage 1: input projections -> SA (rows 0-15: Wp, rows 16-31: Wt) --
    gemm_tile<48, false, true, false>(Wp, Wt, bp, bt,
                                      SB, LDB, SA, LDA, nullptr, 0, cbase, rg);
    __syncthreads();

    // ---- stage 2: packed QKV -> SB[tr][0:576] (3 column passes) ------------
    #pragma unroll
    for (int cb = 0; cb < 576; cb += 192)
        gemm_tile<48, false, false, false>(in_w, in_w, in_b, in_b,
                                           SA, LDA, SB, LDB, nullptr, 0,
                                           cb + cbase, rg);
    __syncthreads();

    // ---- stage 3: 2-token, 3-head attention; ctx overwrites q slots --------
    if (tid < ROWS * 6) {
        const int r = tid / 6, rem = tid % 6;
        const int t = rem & 1, h = rem >> 1;
        const float* q  = SB + (t * ROWS + r) * LDB + h * 64;
        const float* k0 = SB + r * LDB + 192 + h * 64;
        const float* k1 = SB + (ROWS + r) * LDB + 192 + h * 64;
        const float* v0 = SB + r * LDB + 384 + h * 64;
        const float* v1 = SB + (ROWS + r) * LDB + 384 + h * 64;
        float s0 = 0.f, s1 = 0.f;
        #pragma unroll 8
        for (int d = 0; d < 64; d++) {
            const float qd = q[d];
            s0 += qd * k0[d];
            s1 += qd * k1[d];
        }
        s0 *= 0.125f; s1 *= 0.125f;
        const float m = fmaxf(s0, s1);
        const float e0 = expf(s0 - m), e1 = expf(s1 - m);
        const float inv = 1.f / (e0 + e1);
        const float a0 = e0 * inv, a1 = e1 * inv;
        float* ctx = SB + (t * ROWS + r) * LDB + h * 64;  // q slot
        #pragma unroll 8
        for (int d = 0; d < 64; d++) ctx[d] = a0 * v0[d] + a1 * v1[d];
    }
    __syncthreads();

    // ---- stage 4: out-proj + residual(SA) -> SB[tr][384:576] ---------------
    gemm_tile<48, false, false, true>(out_w, out_w, out_b, out_b,
                                      SB, LDB, SB + 384, LDB, SA, LDA,
                                      cbase, rg);
    __syncthreads();

    // ---- stage 5: LN1 -> SA ------------------------------------------------
    layernorm_rows(SB + 384, LDB, SA, LDA, ln1_g, ln1_b, tid);
    __syncthreads();

    // ---- stage 6: FFN up + ReLU -> SB[tr][0:384] (2 passes) ----------------
    #pragma unroll
    for (int cb = 0; cb < 384; cb += 192)
        gemm_tile<48, true, false, false>(ffn_w1, ffn_w1, ffn_b1, ffn_b1,
                                          SA, LDA, SB, LDB, nullptr, 0,
                                          cb + cbase, rg);
    __syncthreads();

    // ---- stage 7: FFN down (K=384) + residual(SA) -> SB[tr][384:576] -------
    gemm_tile<96, false, false, true>(ffn_w2, ffn_w2, ffn_b2, ffn_b2,
                                      SB, LDB, SB + 384, LDB, SA, LDA,
                                      cbase, rg);
    __syncthreads();

    // ---- stage 8: LN2 -> SA ------------------------------------------------
    layernorm_rows(SB + 384, LDB, SA, LDA, ln2_g, ln2_b, tid);
    __syncthreads();

    // ---- stage 9: z = mean over 2 tokens -> SB[r][384:576] -----------------
    for (int i = tid; i < ROWS * 48; i += THREADS) {
        const int r = i / 48, k4 = i % 48;
        const float4 x0 = reinterpret_cast<const float4*>(SA + r * LDA)[k4];
        const float4 x1 = reinterpret_cast<const float4*>(SA + (ROWS + r) * LDA)[k4];
        float4 z;
        z.x = 0.5f * (x0.x + x1.x);
        z.y = 0.5f * (x0.y + x1.y);
        z.z = 0.5f * (x0.z + x1.z);
        z.w = 0.5f * (x0.w + x1.w);
        reinterpret_cast<float4*>(SB + r * LDB + 384)[k4] = z;
    }
    __syncthreads();

    // ---- stage 10: heads. row = lane&15, col-half = lane>>4 ----------------
    {
        const int r  = lane & 15;
        const int hf = lane >> 4;
        const float* zrow = SB + r * LDB + 384;
        // cls hidden (relu): 192 cols -> SB[r][0:192]
        {
            const int c0 = warp * 24 + hf * 12;
            gemm_b<12, 192, true>(cls_w1 + c0 * 192, cls_b1 + c0,
                                  zrow, SB + r * LDB + c0);
        }
        // fingerprint: 128 cols -> SB[r][192:320]
        {
            const int c0 = warp * 16 + hf * 8;
            gemm_b<8, 192, false>(fp_w + c0 * 192, fp_b + c0,
                                  zrow, SB + r * LDB + 192 + c0);
        }
    }
    __syncthreads();

    // ---- stage 11: cls logits + sigmoid -> out[j*B + row] ------------------
    if (tid < ROWS * 3) {
        const int r = tid / 3, j = tid % 3;
        const int gr = block0 + r;
        if (gr < B) {
            const float* hrow = SB + r * LDB;
            const float* w = cls_w2 + j * D;
            float s = cls_b2[j];
            #pragma unroll 8
            for (int k = 0; k < D; k++) s += hrow[k] * w[k];
            out[(size_t)j * B + gr] = 1.f / (1.f + expf(-s));
        }
    }

    // ---- stage 12: fingerprint L2-normalize -> out[3B + row*128 + c] -------
    {
        #pragma unroll
        for (int rr = 0; rr < 2; rr++) {
            const int r = warp * 2 + rr;
            const int gr = block0 + r;
            const float* f = SB + r * LDB + 192;
            float v[4], sq = 0.f;
            #pragma unroll
            for (int j = 0; j < 4; j++) {
                v[j] = f[lane + 32 * j];
                sq += v[j] * v[j];
            }
            #pragma unroll
            for (int o = 16; o; o >>= 1)
                sq += __shfl_xor_sync(0xffffffffu, sq, o);
            const float inv = 1.f / fmaxf(sqrtf(sq), 1e-12f);
            if (gr < B) {
                float* o = out + (size_t)3 * B + (size_t)gr * 128;
                #pragma unroll
                for (int j = 0; j < 4; j++) o[lane + 32 * j] = v[j] * inv;
            }
        }
    }
}

extern "C" void kernel_launch(void* const* d_in, const int* in_sizes, int n_in,
                              void* d_out, int out_size)
{
    const float* perc   = (const float*)d_in[0];
    const float* tech   = (const float*)d_in[1];
    const float* Wp     = (const float*)d_in[2];
    const float* bp     = (const float*)d_in[3];
    const float* Wt     = (const float*)d_in[4];
    const float* bt     = (const float*)d_in[5];
    const float* in_w   = (const float*)d_in[6];
    const float* in_b   = (const float*)d_in[7];
    const float* out_w  = (const float*)d_in[8];
    const float* out_b  = (const float*)d_in[9];
    const float* ffn_w1 = (const float*)d_in[10];
    const float* ffn_b1 = (const float*)d_in[11];
    const float* ffn_w2 = (const float*)d_in[12];
    const float* ffn_b2 = (const float*)d_in[13];
    const float* ln1_g  = (const float*)d_in[14];
    const float* ln1_b  = (const float*)d_in[15];
    const float* ln2_g  = (const float*)d_in[16];
    const float* ln2_b  = (const float*)d_in[17];
    const float* cls_w1 = (const float*)d_in[18];
    const float* cls_b1 = (const float*)d_in[19];
    const float* cls_w2 = (const float*)d_in[20];
    const float* cls_b2 = (const float*)d_in[21];
    const float* fp_w   = (const float*)d_in[22];
    const float* fp_b   = (const float*)d_in[23];

    const int B = in_sizes[0] / D;
    const size_t SMEM = (size_t)(TOK * LDA + TOK * LDB) * sizeof(float);

    cudaFuncSetAttribute(fusion_head_kernel,
                         cudaFuncAttributeMaxDynamicSharedMemorySize, (int)SMEM);

    const int grid = (B + ROWS - 1) / ROWS;
    fusion_head_kernel<<<grid, THREADS, SMEM>>>(
        perc, tech, Wp, bp, Wt, bt, in_w, in_b, out_w, out_b,
        ffn_w1, ffn_b1, ffn_w2, ffn_b2, ln1_g, ln1_b, ln2_g, ln2_b,
        cls_w1, cls_b1, cls_w2, cls_b2, fp_w, fp_b,
        (float*)d_out, B);
}